// round 2
// baseline (speedup 1.0000x reference)
#include <cuda_runtime.h>
#include <cuda_bf16.h>
#include <math.h>

// ---------------------------------------------------------------------------
// MultiheadAttention: b=8, s=1024, d=2048, h=16, hd=128, fp32.
//   q = x@wq^T ; k = x@wk^T ; v = x@wv^T          (8192x2048 @ 2048x2048^T)
//   RoPE over FULL hidden dim on q,k (pairs (2f,2f+1), freq f = col/2)
//   scores = QK^T / sqrt(2048) per (b,h)          (1024x128 @ 128x1024)
//   softmax rows ; ctx = P@V ; out = ctx@wo^T
// ---------------------------------------------------------------------------

#define B_   8
#define S_   1024
#define D_   2048
#define H_   16
#define HD_  128
#define MTOT (B_ * S_)           // 8192

// scratch (no cudaMalloc allowed)
__device__ float g_q  [(size_t)MTOT * D_];
__device__ float g_k  [(size_t)MTOT * D_];
__device__ float g_v  [(size_t)MTOT * D_];
__device__ float g_ctx[(size_t)MTOT * D_];
__device__ float g_p  [(size_t)B_ * H_ * S_ * S_];   // 512 MB scores
__device__ float g_cos[(size_t)S_ * (D_ / 2)];
__device__ float g_sin[(size_t)S_ * (D_ / 2)];

// ---------------------------------------------------------------------------
// RoPE tables: angle = pos * theta^(-2f/d). Computed in double, stored fp32.
// ---------------------------------------------------------------------------
__global__ void rope_tables_k(float* __restrict__ cosT, float* __restrict__ sinT) {
    int idx = blockIdx.x * blockDim.x + threadIdx.x;     // [0, 1024*1024)
    int pos = idx >> 10;
    int f   = idx & 1023;
    double inv = exp(-(double)(2 * f) / (double)D_ * 9.210340371976184);  // ln(10000)
    double a   = (double)pos * inv;
    cosT[idx] = (float)cos(a);
    sinT[idx] = (float)sin(a);
}

// ---------------------------------------------------------------------------
// Tiled SGEMM: C[M,N] = alpha * A @ op(B), 128x128 tile, BK=8, 256 threads,
// 8x8 microtile per thread.
//   TRANSB=true : B is [N,K] row-major (C = A B^T)   -- both operands K-major
//   TRANSB=false: B is [K,N] row-major (C = A B)
//   ROPE=true   : apply full-hidden-dim RoPE rotation in the epilogue
// Batched via blockIdx.z = zb*16 + zh with per-(b)/(h) offsets (0 => unbatched).
// All dims here are multiples of tile sizes: no bounds checks.
// ---------------------------------------------------------------------------
#define TILE 128
#define BK   8

template <bool TRANSB, bool ROPE>
__global__ __launch_bounds__(256)
void gemm_k(const float* __restrict__ A, int lda,
            const float* __restrict__ B, int ldb,
            float* __restrict__ C, int ldc,
            int K, float alpha,
            size_t sAb, size_t sAh, size_t sBb, size_t sBh, size_t sCb, size_t sCh,
            const float* __restrict__ cosT, const float* __restrict__ sinT)
{
    __shared__ float As[BK][TILE];
    __shared__ float Bs[BK][TILE];

    const int z  = blockIdx.z;
    const int zb = z >> 4, zh = z & 15;
    A += (size_t)zb * sAb + (size_t)zh * sAh;
    B += (size_t)zb * sBb + (size_t)zh * sBh;
    C += (size_t)zb * sCb + (size_t)zh * sCh;

    const int t  = threadIdx.x;
    const int tr = t >> 4;          // 0..15 row group
    const int tc = t & 15;          // 0..15 col group
    const int lm = t >> 1;          // 0..127: tile row (A) / tile col (B, NT)
    const int kq = (t & 1) * 4;     // k sub-offset for float4 load

    const float* Aptr = A + (size_t)(blockIdx.y * TILE + lm) * lda + kq;
    const float* Bptr;
    if (TRANSB) {
        Bptr = B + (size_t)(blockIdx.x * TILE + lm) * ldb + kq;
    } else {
        Bptr = B + (size_t)(t >> 5) * ldb + blockIdx.x * TILE + (t & 31) * 4;
    }

    float acc[8][8];
#pragma unroll
    for (int i = 0; i < 8; i++)
#pragma unroll
        for (int j = 0; j < 8; j++) acc[i][j] = 0.f;

    for (int kt = 0; kt < K; kt += BK) {
        float4 av = *(const float4*)(Aptr + kt);
        As[kq + 0][lm] = av.x;
        As[kq + 1][lm] = av.y;
        As[kq + 2][lm] = av.z;
        As[kq + 3][lm] = av.w;
        if (TRANSB) {
            float4 bv = *(const float4*)(Bptr + kt);
            Bs[kq + 0][lm] = bv.x;
            Bs[kq + 1][lm] = bv.y;
            Bs[kq + 2][lm] = bv.z;
            Bs[kq + 3][lm] = bv.w;
        } else {
            float4 bv = *(const float4*)(Bptr + (size_t)kt * ldb);
            *(float4*)&Bs[t >> 5][(t & 31) * 4] = bv;
        }
        __syncthreads();

#pragma unroll
        for (int kk = 0; kk < BK; kk++) {
            float a[8], b[8];
            *(float4*)&a[0] = *(const float4*)&As[kk][tr * 8];
            *(float4*)&a[4] = *(const float4*)&As[kk][tr * 8 + 4];
            *(float4*)&b[0] = *(const float4*)&Bs[kk][tc * 8];
            *(float4*)&b[4] = *(const float4*)&Bs[kk][tc * 8 + 4];
#pragma unroll
            for (int i = 0; i < 8; i++)
#pragma unroll
                for (int j = 0; j < 8; j++)
                    acc[i][j] = fmaf(a[i], b[j], acc[i][j]);
        }
        __syncthreads();
    }

    const int crow = blockIdx.y * TILE + tr * 8;
    const int ccol = blockIdx.x * TILE + tc * 8;
#pragma unroll
    for (int i = 0; i < 8; i++) {
        const int row = crow + i;
        if (ROPE) {
            const int pos = row & (S_ - 1);          // row = b*1024 + s
            const float* cr = cosT + (size_t)pos * (D_ / 2);
            const float* sr = sinT + (size_t)pos * (D_ / 2);
#pragma unroll
            for (int j = 0; j < 8; j += 2) {
                const int f = (ccol + j) >> 1;
                float c = cr[f], s = sr[f];
                float v0 = acc[i][j], v1 = acc[i][j + 1];
                acc[i][j]     = v0 * c - v1 * s;
                acc[i][j + 1] = v0 * s + v1 * c;
            }
        }
        float4 o0 = make_float4(acc[i][0] * alpha, acc[i][1] * alpha,
                                acc[i][2] * alpha, acc[i][3] * alpha);
        float4 o1 = make_float4(acc[i][4] * alpha, acc[i][5] * alpha,
                                acc[i][6] * alpha, acc[i][7] * alpha);
        *(float4*)(C + (size_t)row * ldc + ccol)     = o0;
        *(float4*)(C + (size_t)row * ldc + ccol + 4) = o1;
    }
}

// ---------------------------------------------------------------------------
// Row softmax over 1024 elements: 1 block/row, 256 threads, 1 float4/thread.
// ---------------------------------------------------------------------------
__global__ __launch_bounds__(256)
void softmax_k(float* __restrict__ P) {
    float4* row = (float4*)(P + (size_t)blockIdx.x * S_);
    const int t = threadIdx.x;
    __shared__ float red[256];

    float4 v = row[t];
    float m = fmaxf(fmaxf(v.x, v.y), fmaxf(v.z, v.w));
    red[t] = m;
    __syncthreads();
    for (int s = 128; s > 0; s >>= 1) {
        if (t < s) red[t] = fmaxf(red[t], red[t + s]);
        __syncthreads();
    }
    m = red[0];
    __syncthreads();

    v.x = expf(v.x - m); v.y = expf(v.y - m);
    v.z = expf(v.z - m); v.w = expf(v.w - m);
    red[t] = v.x + v.y + v.z + v.w;
    __syncthreads();
    for (int s = 128; s > 0; s >>= 1) {
        if (t < s) red[t] += red[t + s];
        __syncthreads();
    }
    const float inv = 1.f / red[0];
    v.x *= inv; v.y *= inv; v.z *= inv; v.w *= inv;
    row[t] = v;
}

// ---------------------------------------------------------------------------
extern "C" void kernel_launch(void* const* d_in, const int* in_sizes, int n_in,
                              void* d_out, int out_size) {
    const float* x  = (const float*)d_in[0];
    const float* wq = (const float*)d_in[1];
    const float* wk = (const float*)d_in[2];
    const float* wv = (const float*)d_in[3];
    const float* wo = (const float*)d_in[4];
    float* out = (float*)d_out;

    float *q, *k, *v, *ctx, *p, *ct, *st;
    cudaGetSymbolAddress((void**)&q,   g_q);
    cudaGetSymbolAddress((void**)&k,   g_k);
    cudaGetSymbolAddress((void**)&v,   g_v);
    cudaGetSymbolAddress((void**)&ctx, g_ctx);
    cudaGetSymbolAddress((void**)&p,   g_p);
    cudaGetSymbolAddress((void**)&ct,  g_cos);
    cudaGetSymbolAddress((void**)&st,  g_sin);

    // 1. RoPE tables (1024 x 1024)
    rope_tables_k<<<(S_ * (D_ / 2)) / 256, 256>>>(ct, st);

    // 2. Projections: [8192,2048] = x @ w^T  (NT). RoPE fused for Q,K.
    dim3 gProj(D_ / TILE, MTOT / TILE, 1);   // (16, 64, 1)
    gemm_k<true, true ><<<gProj, 256>>>(x, D_, wq, D_, q, D_, D_, 1.f,
                                        0, 0, 0, 0, 0, 0, ct, st);
    gemm_k<true, true ><<<gProj, 256>>>(x, D_, wk, D_, k, D_, D_, 1.f,
                                        0, 0, 0, 0, 0, 0, ct, st);
    gemm_k<true, false><<<gProj, 256>>>(x, D_, wv, D_, v, D_, D_, 1.f,
                                        0, 0, 0, 0, 0, 0, nullptr, nullptr);

    // 3. scores = Q K^T / sqrt(2048), batched over 128 (b,h). NT, K=128.
    const float alpha = 1.0f / sqrtf((float)D_);
    dim3 gS(S_ / TILE, S_ / TILE, B_ * H_);  // (8, 8, 128)
    gemm_k<true, false><<<gS, 256>>>(q, D_, k, D_, p, S_, HD_, alpha,
                                     (size_t)S_ * D_, (size_t)HD_,
                                     (size_t)S_ * D_, (size_t)HD_,
                                     (size_t)H_ * S_ * S_, (size_t)S_ * S_,
                                     nullptr, nullptr);

    // 4. softmax over last axis (131072 rows of 1024)
    softmax_k<<<B_ * H_ * S_, 256>>>(p);

    // 5. ctx = P @ V, batched. NN (V is [S, hd] with row stride 2048).
    dim3 gC(HD_ / TILE, S_ / TILE, B_ * H_); // (1, 8, 128)
    gemm_k<false, false><<<gC, 256>>>(p, S_, v, D_, ctx, D_, S_, 1.f,
                                      (size_t)H_ * S_ * S_, (size_t)S_ * S_,
                                      (size_t)S_ * D_, (size_t)HD_,
                                      (size_t)S_ * D_, (size_t)HD_,
                                      nullptr, nullptr);

    // 6. out = ctx @ wo^T  (NT)
    gemm_k<true, false><<<gProj, 256>>>(ctx, D_, wo, D_, out, D_, D_, 1.f,
                                        0, 0, 0, 0, 0, 0, nullptr, nullptr);
}

// round 4
// speedup vs baseline: 2.4886x; 2.4886x over previous
#include <cuda_runtime.h>
#include <cuda_bf16.h>
#include <math.h>
#include <stdint.h>

#define B_   8
#define S_   1024
#define D_   2048
#define H_   16
#define HD_  128
#define MTOT (B_*S_)
#define BH_  (B_*H_)
#define K3P  (3*D_)
#define K3S  (3*HD_)
#define K3C  (3*S_)

__device__ __nv_bfloat16 g_xs  [(size_t)MTOT*K3P];
__device__ __nv_bfloat16 g_wqs [(size_t)D_*K3P];
__device__ __nv_bfloat16 g_wks [(size_t)D_*K3P];
__device__ __nv_bfloat16 g_wvs [(size_t)D_*K3P];
__device__ __nv_bfloat16 g_wos [(size_t)D_*K3P];
__device__ __nv_bfloat16 g_qs  [(size_t)BH_*S_*K3S];
__device__ __nv_bfloat16 g_ks  [(size_t)BH_*S_*K3S];
__device__ float         g_v   [(size_t)MTOT*D_];
__device__ __nv_bfloat16 g_vt  [(size_t)BH_*HD_*K3C];
__device__ float         g_p   [(size_t)BH_*S_*S_];
__device__ __nv_bfloat16 g_ps  [(size_t)BH_*S_*K3C];
__device__ __nv_bfloat16 g_ctxs[(size_t)MTOT*K3P];
__device__ float g_cos[(size_t)S_*(D_/2)];
__device__ float g_sin[(size_t)S_*(D_/2)];

__device__ __forceinline__ uint32_t smem_u32(const void* p) {
    uint32_t a;
    asm("{ .reg .u64 t; cvta.to.shared.u64 t, %1; cvt.u32.u64 %0, t; }" : "=r"(a) : "l"(p));
    return a;
}
__device__ __forceinline__ void cp16(uint32_t dst, const void* src) {
    asm volatile("cp.async.cg.shared.global [%0], [%1], 16;" :: "r"(dst), "l"(src));
}
#define CP_COMMIT() asm volatile("cp.async.commit_group;" ::: "memory")
#define CP_WAIT2()  asm volatile("cp.async.wait_group 2;" ::: "memory")

#define LDSM4(r, addr)                                                         \
    asm volatile("ldmatrix.sync.aligned.m8n8.x4.shared.b16 {%0,%1,%2,%3}, [%4];" \
        : "=r"((r)[0]),"=r"((r)[1]),"=r"((r)[2]),"=r"((r)[3]) : "r"(addr))

#define MMA(d, a, b0r, b1r)                                                    \
    asm volatile("mma.sync.aligned.m16n8k16.row.col.f32.bf16.bf16.f32 "        \
        "{%0,%1,%2,%3}, {%4,%5,%6,%7}, {%8,%9}, {%0,%1,%2,%3};"                \
        : "+f"((d)[0]),"+f"((d)[1]),"+f"((d)[2]),"+f"((d)[3])                  \
        : "r"((a)[0]),"r"((a)[1]),"r"((a)[2]),"r"((a)[3]), "r"(b0r),"r"(b1r))

__device__ __forceinline__ uint32_t pack_hi(float a, float b, float* la, float* lb) {
    __nv_bfloat162 p;
    p.x = __float2bfloat16(a); p.y = __float2bfloat16(b);
    *la = a - __bfloat162float(p.x);
    *lb = b - __bfloat162float(p.y);
    return *(uint32_t*)&p;
}
__device__ __forceinline__ uint32_t pack_bf2(float a, float b) {
    __nv_bfloat162 p;
    p.x = __float2bfloat16(a); p.y = __float2bfloat16(b);
    return *(uint32_t*)&p;
}

// smem tile: 128 rows x 32 bf16 (64B/row), chunk swizzle ch^((row>>1)&3)
__device__ __forceinline__ void load_tile(uint32_t sbase, const __nv_bfloat16* g,
                                          int ld, int t) {
#pragma unroll
    for (int i = 0; i < 2; i++) {
        int lin = t + 256*i, row = lin >> 2, ch = lin & 3;
        uint32_t sw = row*64 + ((ch ^ ((row >> 1) & 3)) << 4);
        cp16(sbase + sw, g + (size_t)row*ld + ch*8);
    }
}

// ===========================================================================
// mma.sync bf16 GEMM: C[M,N] = alpha * A'[M,K3] @ B'[N,K3]^T
// CTA 128x128, BK=32, 4-stage cp.async, 8 warps (2M x 4N), warp 64x32.
// EPI 0: fp32 out. EPI 1: RoPE+split -> [b,h,s,384]. EPI 2: split -> [8192,6144]
// ===========================================================================
template <int EPI>
__global__ __launch_bounds__(256) void tgemm(
    const __nv_bfloat16* __restrict__ A, int lda,
    const __nv_bfloat16* __restrict__ B, int ldb,
    float* __restrict__ Cf, __nv_bfloat16* __restrict__ Cs, int ldc,
    int K3, float alpha, size_t sA, size_t sB, size_t sC,
    int offHi2, int offLo,
    const float* __restrict__ cosT, const float* __restrict__ sinT)
{
    extern __shared__ __align__(1024) char dsm[];
    const uint32_t smem0 = smem_u32(dsm);

    const int t = threadIdx.x, lane = t & 31, w = t >> 5;
    const int wm = w >> 2, wn = w & 3;             // warp tile (wm*64, wn*32)
    const int z = blockIdx.z;
    const int m0 = blockIdx.y * 128, n0 = blockIdx.x * 128;
    const __nv_bfloat16* At = A + (size_t)z*sA + (size_t)m0*lda;
    const __nv_bfloat16* Bt = B + (size_t)z*sB + (size_t)n0*ldb;

    float acc[4][4][4];
#pragma unroll
    for (int i = 0; i < 4; i++)
#pragma unroll
        for (int j = 0; j < 4; j++)
#pragma unroll
            for (int c = 0; c < 4; c++) acc[i][j][c] = 0.f;

    const int NS = K3 / 32;
    // prologue: stages 0..2
#pragma unroll
    for (int st = 0; st < 3; st++) {
        load_tile(smem0 + st*16384,        At + st*32, lda, t);
        load_tile(smem0 + st*16384 + 8192, Bt + st*32, ldb, t);
        CP_COMMIT();
    }

    const int l15 = lane & 15, l16 = lane >> 4;

    for (int s = 0; s < NS; s++) {
        CP_WAIT2();
        __syncthreads();
        if (s + 3 < NS) {
            const int st = (s + 3) & 3;
            load_tile(smem0 + st*16384,        At + (s+3)*32, lda, t);
            load_tile(smem0 + st*16384 + 8192, Bt + (s+3)*32, ldb, t);
        }
        CP_COMMIT();

        const uint32_t sAb = smem0 + (s & 3)*16384;
        const uint32_t sBb = sAb + 8192;
#pragma unroll
        for (int ks = 0; ks < 2; ks++) {
            uint32_t a[4][4], b[2][4];
#pragma unroll
            for (int mi = 0; mi < 4; mi++) {
                int r  = wm*64 + mi*16 + l15;
                int ch = ks*2 + l16;
                LDSM4(a[mi], sAb + r*64 + ((ch ^ ((r >> 1) & 3)) << 4));
            }
#pragma unroll
            for (int nj = 0; nj < 2; nj++) {
                int r  = wn*32 + nj*16 + l15;
                int ch = ks*2 + l16;
                LDSM4(b[nj], sBb + r*64 + ((ch ^ ((r >> 1) & 3)) << 4));
            }
#pragma unroll
            for (int mi = 0; mi < 4; mi++)
#pragma unroll
                for (int ni = 0; ni < 4; ni++)
                    MMA(acc[mi][ni], a[mi], b[ni >> 1][ni & 1], b[ni >> 1][(ni & 1) + 2]);
        }
    }

    // ------------------------------ epilogue -------------------------------
    const int gi = lane >> 2, t4 = lane & 3;
#pragma unroll
    for (int mi = 0; mi < 4; mi++) {
#pragma unroll
        for (int half = 0; half < 2; half++) {
            const int row = m0 + wm*64 + mi*16 + gi + half*8;
            if (EPI == 0) {
                float* dst = Cf + (size_t)z*sC + (size_t)row*ldc + n0;
#pragma unroll
                for (int ni = 0; ni < 4; ni++) {
                    int lc = wn*32 + ni*8 + t4*2;
                    float2 o = make_float2(acc[mi][ni][half*2]   * alpha,
                                           acc[mi][ni][half*2+1] * alpha);
                    *(float2*)(dst + lc) = o;
                }
            } else if (EPI == 1) {
                const int pos = row & (S_-1), bb = row >> 10, h = blockIdx.x;
                const float* cr = cosT + (size_t)pos*(D_/2);
                const float* sr = sinT + (size_t)pos*(D_/2);
                __nv_bfloat16* dst = Cs + ((size_t)(bb*H_ + h)*S_ + pos)*K3S;
#pragma unroll
                for (int ni = 0; ni < 4; ni++) {
                    int lc = wn*32 + ni*8 + t4*2;
                    int fi = (h*HD_ + lc) >> 1;
                    float c = cr[fi], sn = sr[fi];
                    float v0 = acc[mi][ni][half*2], v1 = acc[mi][ni][half*2+1];
                    float r0 = v0*c - v1*sn, r1 = v0*sn + v1*c;
                    float la, lb;
                    uint32_t hi = pack_hi(r0, r1, &la, &lb);
                    uint32_t lo = pack_bf2(la, lb);
                    *(uint32_t*)(dst + lc)          = hi;
                    *(uint32_t*)(dst + lc + offHi2) = hi;
                    *(uint32_t*)(dst + lc + offLo)  = lo;
                }
            } else {
                const int bb = z >> 4, h = z & 15;
                __nv_bfloat16* dst = Cs + (size_t)(bb*S_ + row)*K3P + h*HD_;
#pragma unroll
                for (int ni = 0; ni < 4; ni++) {
                    int lc = wn*32 + ni*8 + t4*2;
                    float la, lb;
                    uint32_t hi = pack_hi(acc[mi][ni][half*2], acc[mi][ni][half*2+1],
                                          &la, &lb);
                    uint32_t lo = pack_bf2(la, lb);
                    *(uint32_t*)(dst + lc)          = hi;
                    *(uint32_t*)(dst + lc + offHi2) = hi;
                    *(uint32_t*)(dst + lc + offLo)  = lo;
                }
            }
        }
    }
}

// fp32 [R,2048] -> split bf16 [R,6144]
__global__ __launch_bounds__(256) void conv_split_k(
    const float4* __restrict__ in, __nv_bfloat16* __restrict__ out,
    int offHi2, int offLo, int nchunk)
{
    int i = blockIdx.x*256 + threadIdx.x;
    if (i >= nchunk) return;
    int r = i >> 8, c = (i & 255)*8;
    float4 v0 = in[i*2], v1 = in[i*2+1];
    float f[8] = {v0.x,v0.y,v0.z,v0.w,v1.x,v1.y,v1.z,v1.w};
    uint32_t hh[4], ll[4];
#pragma unroll
    for (int j = 0; j < 4; j++) {
        float la, lb;
        hh[j] = pack_hi(f[2*j], f[2*j+1], &la, &lb);
        ll[j] = pack_bf2(la, lb);
    }
    uint4 vh = make_uint4(hh[0],hh[1],hh[2],hh[3]);
    uint4 vl = make_uint4(ll[0],ll[1],ll[2],ll[3]);
    __nv_bfloat16* dst = out + (size_t)r*K3P + c;
    *(uint4*)dst = vh;
    *(uint4*)(dst + offHi2) = vh;
    *(uint4*)(dst + offLo)  = vl;
}

// V [b,s,h,hd] fp32 -> VT [bh,n,3072] bf16 (hi|lo|hi)
__global__ __launch_bounds__(256) void vsplit_k(
    const float* __restrict__ V, __nv_bfloat16* __restrict__ VT)
{
    __shared__ float tile[32][33];
    const int bh = blockIdx.x, b = bh >> 4, h = bh & 15;
    const int k0 = blockIdx.y*32, n0 = blockIdx.z*32;
    const int r = threadIdx.x >> 5, c = threadIdx.x & 31;
#pragma unroll
    for (int i = 0; i < 4; i++)
        tile[r + i*8][c] = V[((size_t)(b*S_ + k0 + r + i*8))*D_ + h*HD_ + n0 + c];
    __syncthreads();
#pragma unroll
    for (int i = 0; i < 4; i++) {
        int n = n0 + r + i*8;
        float v = tile[c][r + i*8];
        __nv_bfloat16 hi = __float2bfloat16(v);
        __nv_bfloat16 lo = __float2bfloat16(v - __bfloat162float(hi));
        __nv_bfloat16* dst = VT + ((size_t)bh*HD_ + n)*K3C + k0 + c;
        dst[0]     = hi;
        dst[S_]    = lo;
        dst[2*S_]  = hi;
    }
}

// softmax over 1024 + split-write [row,3072] (hi|hi|lo)
__global__ __launch_bounds__(256) void softmax_split_k(
    const float* __restrict__ P, __nv_bfloat16* __restrict__ PS)
{
    const float4* row = (const float4*)(P + (size_t)blockIdx.x*S_);
    const int t = threadIdx.x;
    __shared__ float red[256];
    float4 v = row[t];
    float m = fmaxf(fmaxf(v.x, v.y), fmaxf(v.z, v.w));
    red[t] = m; __syncthreads();
    for (int s = 128; s > 0; s >>= 1) { if (t < s) red[t] = fmaxf(red[t], red[t+s]); __syncthreads(); }
    m = red[0]; __syncthreads();
    v.x = expf(v.x - m); v.y = expf(v.y - m);
    v.z = expf(v.z - m); v.w = expf(v.w - m);
    red[t] = v.x + v.y + v.z + v.w; __syncthreads();
    for (int s = 128; s > 0; s >>= 1) { if (t < s) red[t] += red[t+s]; __syncthreads(); }
    const float inv = 1.f / red[0];
    float f[4] = { v.x*inv, v.y*inv, v.z*inv, v.w*inv };
    float la0, lb0, la1, lb1;
    uint32_t h0 = pack_hi(f[0], f[1], &la0, &lb0);
    uint32_t h1 = pack_hi(f[2], f[3], &la1, &lb1);
    uint32_t l0 = pack_bf2(la0, lb0), l1 = pack_bf2(la1, lb1);
    __nv_bfloat16* dst = PS + (size_t)blockIdx.x*K3C + t*4;
    *(uint2*)dst          = make_uint2(h0, h1);
    *(uint2*)(dst + S_)   = make_uint2(h0, h1);
    *(uint2*)(dst + 2*S_) = make_uint2(l0, l1);
}

__global__ void rope_tables_k(float* __restrict__ cosT, float* __restrict__ sinT) {
    int idx = blockIdx.x*blockDim.x + threadIdx.x;
    int pos = idx >> 10, f = idx & 1023;
    double inv = exp(-(double)(2*f)/(double)D_ * 9.210340371976184);
    double a = (double)pos * inv;
    cosT[idx] = (float)cos(a);
    sinT[idx] = (float)sin(a);
}

extern "C" void kernel_launch(void* const* d_in, const int* in_sizes, int n_in,
                              void* d_out, int out_size) {
    const float* x  = (const float*)d_in[0];
    const float* wq = (const float*)d_in[1];
    const float* wk = (const float*)d_in[2];
    const float* wv = (const float*)d_in[3];
    const float* wo = (const float*)d_in[4];
    float* out = (float*)d_out;

    __nv_bfloat16 *xs,*wqs,*wks,*wvs,*wos,*qs,*ks,*vt,*ps,*ctxs;
    float *v,*p,*ct,*st;
    cudaGetSymbolAddress((void**)&xs, g_xs);
    cudaGetSymbolAddress((void**)&wqs, g_wqs);
    cudaGetSymbolAddress((void**)&wks, g_wks);
    cudaGetSymbolAddress((void**)&wvs, g_wvs);
    cudaGetSymbolAddress((void**)&wos, g_wos);
    cudaGetSymbolAddress((void**)&qs, g_qs);
    cudaGetSymbolAddress((void**)&ks, g_ks);
    cudaGetSymbolAddress((void**)&v, g_v);
    cudaGetSymbolAddress((void**)&vt, g_vt);
    cudaGetSymbolAddress((void**)&p, g_p);
    cudaGetSymbolAddress((void**)&ps, g_ps);
    cudaGetSymbolAddress((void**)&ctxs, g_ctxs);
    cudaGetSymbolAddress((void**)&ct, g_cos);
    cudaGetSymbolAddress((void**)&st, g_sin);

    const int SMEM = 65536;
    cudaFuncSetAttribute(tgemm<0>, cudaFuncAttributeMaxDynamicSharedMemorySize, SMEM);
    cudaFuncSetAttribute(tgemm<1>, cudaFuncAttributeMaxDynamicSharedMemorySize, SMEM);
    cudaFuncSetAttribute(tgemm<2>, cudaFuncAttributeMaxDynamicSharedMemorySize, SMEM);

    rope_tables_k<<<(S_*(D_/2))/256, 256>>>(ct, st);

    const int xn = MTOT*D_/8, wn = D_*D_/8;
    conv_split_k<<<xn/256, 256>>>((const float4*)x,  xs,  D_, 2*D_, xn);   // A: hi|hi|lo
    conv_split_k<<<wn/256, 256>>>((const float4*)wq, wqs, 2*D_, D_, wn);   // B: hi|lo|hi
    conv_split_k<<<wn/256, 256>>>((const float4*)wk, wks, 2*D_, D_, wn);
    conv_split_k<<<wn/256, 256>>>((const float4*)wv, wvs, 2*D_, D_, wn);
    conv_split_k<<<wn/256, 256>>>((const float4*)wo, wos, 2*D_, D_, wn);

    dim3 gProj(16, 64, 1);
    tgemm<1><<<gProj, 256, SMEM>>>(xs, K3P, wqs, K3P, nullptr, qs, 0, K3P, 1.f,
                                   0, 0, 0, 128, 256, ct, st);          // Q: hi,hi,lo
    tgemm<1><<<gProj, 256, SMEM>>>(xs, K3P, wks, K3P, nullptr, ks, 0, K3P, 1.f,
                                   0, 0, 0, 256, 128, ct, st);          // K: hi,lo,hi
    tgemm<0><<<gProj, 256, SMEM>>>(xs, K3P, wvs, K3P, v, nullptr, D_, K3P, 1.f,
                                   0, 0, 0, 0, 0, nullptr, nullptr);

    vsplit_k<<<dim3(BH_, 32, 4), 256>>>(v, vt);

    const float alpha = 1.0f / sqrtf((float)D_);
    tgemm<0><<<dim3(8, 8, BH_), 256, SMEM>>>(qs, K3S, ks, K3S, p, nullptr, S_,
                                             K3S, alpha,
                                             (size_t)S_*K3S, (size_t)S_*K3S, (size_t)S_*S_,
                                             0, 0, nullptr, nullptr);

    softmax_split_k<<<BH_*S_, 256>>>(p, ps);

    tgemm<2><<<dim3(1, 8, BH_), 256, SMEM>>>(ps, K3C, vt, K3C, nullptr, ctxs, 0,
                                             K3C, 1.f,
                                             (size_t)S_*K3C, (size_t)HD_*K3C, 0,
                                             D_, 2*D_, nullptr, nullptr);   // ctx: hi,hi,lo

    tgemm<0><<<gProj, 256, SMEM>>>(ctxs, K3P, wos, K3P, out, nullptr, D_, K3P, 1.f,
                                   0, 0, 0, 0, 0, nullptr, nullptr);
}